// round 1
// baseline (speedup 1.0000x reference)
#include <cuda_runtime.h>
#include <cstdint>
#include <cstddef>

// Problem constants
#define BB   128            // graphs
#define NL   64             // nodes per graph
#define DEG  16
#define EE   131072         // edges = BB*NL*DEG
#define NN   8192           // total nodes = BB*NL
#define CE   64
#define CH   256            // 4*CE hidden
#define KD   4096           // 64 k * 64 d

// -------------------- device scratch (static, no allocation) --------------------
__device__ float g_h5 [NN * 64];
__device__ float g_t1 [EE * 64];
__device__ float g_t2 [EE * 64];
__device__ float g_X3 [EE * 64];
__device__ float g_Y4 [EE * 64];
__device__ float g_tmp[EE * 256];      // tmp; later reused as z (8192*4096 == EE*256)
__device__ float g_e1 [EE * 256];      // edge MLP hidden (LN+gelu in place)
__device__ float g_agg[NN * 64];
__device__ float g_n1 [NN * 256];
__device__ float g_wr [64 * KD];       // Wagg transposed: [c][k*64+d]
__device__ int   g_adj[BB * NL * NL];  // edge id or -1

// -------------------- generic fp32 GEMM: C[M,N] = A[M,K] @ B[K,N] --------------------
// 64x64 tile, 256 threads, 4x4 microtile, K chunk 16. M%64==0, N%64==0, K%16==0.
__global__ void __launch_bounds__(256) k_gemm(const float* __restrict__ A,
                                              const float* __restrict__ B,
                                              float* __restrict__ C,
                                              int M, int N, int K) {
    __shared__ float As[16][68];
    __shared__ float Bs[16][64];
    const int tid = threadIdx.x;
    const int m0 = blockIdx.y * 64, n0 = blockIdx.x * 64;
    const int ty = tid >> 4, tx = tid & 15;
    const int lm = tid >> 2, lkq = tid & 3;   // A tile loader
    const int lkr = tid >> 4, lnq = tid & 15; // B tile loader

    float acc[4][4] = {};

    for (int k0 = 0; k0 < K; k0 += 16) {
        float4 av = *(const float4*)(A + (size_t)(m0 + lm) * K + k0 + lkq * 4);
        As[lkq * 4 + 0][lm] = av.x;
        As[lkq * 4 + 1][lm] = av.y;
        As[lkq * 4 + 2][lm] = av.z;
        As[lkq * 4 + 3][lm] = av.w;
        *(float4*)(&Bs[lkr][lnq * 4]) =
            *(const float4*)(B + (size_t)(k0 + lkr) * N + n0 + lnq * 4);
        __syncthreads();
#pragma unroll
        for (int k = 0; k < 16; k++) {
            float4 a = *(const float4*)(&As[k][ty * 4]);
            float4 b = *(const float4*)(&Bs[k][tx * 4]);
            acc[0][0] += a.x * b.x; acc[0][1] += a.x * b.y; acc[0][2] += a.x * b.z; acc[0][3] += a.x * b.w;
            acc[1][0] += a.y * b.x; acc[1][1] += a.y * b.y; acc[1][2] += a.y * b.z; acc[1][3] += a.y * b.w;
            acc[2][0] += a.z * b.x; acc[2][1] += a.z * b.y; acc[2][2] += a.z * b.z; acc[2][3] += a.z * b.w;
            acc[3][0] += a.w * b.x; acc[3][1] += a.w * b.y; acc[3][2] += a.w * b.z; acc[3][3] += a.w * b.w;
        }
        __syncthreads();
    }
#pragma unroll
    for (int i = 0; i < 4; i++) {
        float4 o = make_float4(acc[i][0], acc[i][1], acc[i][2], acc[i][3]);
        *(float4*)(C + (size_t)(m0 + ty * 4 + i) * N + n0 + tx * 4) = o;
    }
}

// -------------------- adjacency --------------------
__global__ void k_adj_init() {
    int i = blockIdx.x * blockDim.x + threadIdx.x;
    if (i < BB * NL * NL) g_adj[i] = -1;
}
__global__ void k_adj_fill(const int* __restrict__ EI) {
    int e = blockIdx.x * blockDim.x + threadIdx.x;
    if (e >= EE) return;
    int base = EI[e];
    int li = EI[EE + e] - base;
    int lj = EI[2 * EE + e] - base;
    int b = base >> 6;
    g_adj[b * (NL * NL) + li * NL + lj] = e;
}

// -------------------- assemble tmp[:,0:192] --------------------
// tmp[:,0:64]=C ; tmp[:,64:128]=(C@W1)*(C@W2) ; tmp[:,128:192]= selfloop ? h5[src] : 0
__global__ void k_assemble(const float* __restrict__ Cin, const int* __restrict__ EI) {
    int idx = blockIdx.x * blockDim.x + threadIdx.x;  // EE*64
    int e = idx >> 6, c = idx & 63;
    size_t row = (size_t)e * 256;
    g_tmp[row + c] = Cin[idx];
    g_tmp[row + 64 + c] = g_t1[idx] * g_t2[idx];
    int s = EI[EE + e], d = EI[2 * EE + e];
    g_tmp[row + 128 + c] = (s == d) ? g_h5[(size_t)s * 64 + c] : 0.0f;
}

// -------------------- tmp_mm -> tmp[:,192:256] --------------------
__global__ void k_mm(const int* __restrict__ EI) {
    int idx = blockIdx.x * blockDim.x + threadIdx.x;  // EE*64
    int e = idx >> 6, c = idx & 63;
    int base = EI[e];
    int li = EI[EE + e] - base;
    int lj = EI[2 * EE + e] - base;
    int b = base >> 6;
    const int* arow = g_adj + b * (NL * NL);
    float acc = 0.0f;
    for (int k = 0; k < NL; k++) {
        int e1 = arow[li * NL + k];
        int e2 = arow[k * NL + lj];
        if (e1 >= 0 && e2 >= 0)
            acc += g_X3[(size_t)e1 * 64 + c] * g_Y4[(size_t)e2 * 64 + c];
    }
    g_tmp[(size_t)e * 256 + 192 + c] = acc;
}

// -------------------- LayerNorm(256) + exact GELU, in-place --------------------
__global__ void k_ln_gelu(float* __restrict__ data,
                          const float* __restrict__ gam,
                          const float* __restrict__ bet) {
    __shared__ float red[8];
    __shared__ float stat[2];
    size_t row = blockIdx.x;
    int t = threadIdx.x;
    float v = data[row * 256 + t];

    float s = v;
#pragma unroll
    for (int o = 16; o > 0; o >>= 1) s += __shfl_down_sync(0xffffffffu, s, o);
    if ((t & 31) == 0) red[t >> 5] = s;
    __syncthreads();
    if (t == 0) {
        float tt = 0.f;
        for (int i = 0; i < 8; i++) tt += red[i];
        stat[0] = tt * (1.0f / 256.0f);
    }
    __syncthreads();
    float mu = stat[0];
    float dv = v - mu;
    float s2 = dv * dv;
#pragma unroll
    for (int o = 16; o > 0; o >>= 1) s2 += __shfl_down_sync(0xffffffffu, s2, o);
    __syncthreads();  // protect red[] reuse
    if ((t & 31) == 0) red[t >> 5] = s2;
    __syncthreads();
    if (t == 0) {
        float tt = 0.f;
        for (int i = 0; i < 8; i++) tt += red[i];
        stat[1] = rsqrtf(tt * (1.0f / 256.0f) + 1e-5f);
    }
    __syncthreads();
    float y = dv * stat[1] * gam[t] + bet[t];
    float out = 0.5f * y * (1.0f + erff(y * 0.70710678118654752440f));
    data[row * 256 + t] = out;
}

// -------------------- Wagg transpose: wr[c][k*64+d] = Wagg[k][c][d] --------------------
__global__ void k_wagg_t(const float* __restrict__ W) {
    int idx = blockIdx.x * blockDim.x + threadIdx.x;  // 262144
    if (idx >= 64 * KD) return;
    int k = idx >> 12, c = (idx >> 6) & 63, d = idx & 63;
    g_wr[c * KD + k * 64 + d] = W[idx];
}

// -------------------- agg[n,d] = sum_{e in out(n)} sum_k Cout[e,k] * z[dst(e), k*64+d] ----
__global__ void k_agg(const float* __restrict__ Cout) {
    int sub = threadIdx.x >> 6;
    int d = threadIdx.x & 63;
    int n = blockIdx.x * 4 + sub;
    int b = n >> 6, i = n & 63;
    const int* arow = g_adj + b * (NL * NL) + i * NL;
    const float* z = g_tmp;  // reused buffer
    float acc = 0.0f;
    for (int j = 0; j < NL; j++) {
        int e = arow[j];
        if (e < 0) continue;
        const float* crow = Cout + (size_t)e * 64;
        const float* zrow = z + (size_t)(b * NL + j) * KD + d;
#pragma unroll
        for (int k = 0; k < 64; k++) acc += crow[k] * zrow[k * 64];
    }
    g_agg[(size_t)n * 64 + d] = acc;
}

// -------------------- launch --------------------
static inline void gemm(const float* A, const float* B, float* C, int M, int N, int K) {
    dim3 g(N / 64, M / 64);
    k_gemm<<<g, 256>>>(A, B, C, M, N, K);
}

extern "C" void kernel_launch(void* const* d_in, const int* in_sizes, int n_in,
                              void* d_out, int out_size) {
    const float* x    = (const float*)d_in[0];   // [8192,64]
    const float* Cin  = (const float*)d_in[1];   // [131072,64]
    const float* W1   = (const float*)d_in[2];
    const float* W2   = (const float*)d_in[3];
    const float* W3   = (const float*)d_in[4];
    const float* W4   = (const float*)d_in[5];
    const float* W5   = (const float*)d_in[6];
    const float* We1  = (const float*)d_in[7];   // [256,256]
    const float* lneg = (const float*)d_in[8];
    const float* lneb = (const float*)d_in[9];
    const float* We2  = (const float*)d_in[10];  // [256,64]
    const float* Wn1  = (const float*)d_in[11];  // [64,256]
    const float* lnng = (const float*)d_in[12];
    const float* lnnb = (const float*)d_in[13];
    const float* Wn2  = (const float*)d_in[14];  // [256,64]
    const float* Wagg = (const float*)d_in[15];  // [64,64,64]
    const int*   EI   = (const int*)d_in[16];    // [3,131072]

    float* xout = (float*)d_out;                 // [8192,64]
    float* Cout = (float*)d_out + (size_t)NN * 64;  // [131072,64]

    float *p_h5, *p_t1, *p_t2, *p_X3, *p_Y4, *p_tmp, *p_e1, *p_agg, *p_n1, *p_wr;
    int* p_adj;
    cudaGetSymbolAddress((void**)&p_h5, g_h5);
    cudaGetSymbolAddress((void**)&p_t1, g_t1);
    cudaGetSymbolAddress((void**)&p_t2, g_t2);
    cudaGetSymbolAddress((void**)&p_X3, g_X3);
    cudaGetSymbolAddress((void**)&p_Y4, g_Y4);
    cudaGetSymbolAddress((void**)&p_tmp, g_tmp);
    cudaGetSymbolAddress((void**)&p_e1, g_e1);
    cudaGetSymbolAddress((void**)&p_agg, g_agg);
    cudaGetSymbolAddress((void**)&p_n1, g_n1);
    cudaGetSymbolAddress((void**)&p_wr, g_wr);
    cudaGetSymbolAddress((void**)&p_adj, g_adj);
    (void)p_adj;

    // adjacency
    k_adj_init<<<(BB * NL * NL + 255) / 256, 256>>>();
    k_adj_fill<<<(EE + 255) / 256, 256>>>(EI);

    // small pre-GEMMs
    gemm(x,   W5, p_h5, NN, 64, 64);
    gemm(Cin, W1, p_t1, EE, 64, 64);
    gemm(Cin, W2, p_t2, EE, 64, 64);
    gemm(Cin, W3, p_X3, EE, 64, 64);
    gemm(Cin, W4, p_Y4, EE, 64, 64);

    // assemble tmp
    k_assemble<<<(EE * 64) / 256, 256>>>(Cin, EI);
    k_mm<<<(EE * 64) / 256, 256>>>(EI);

    // edge MLP
    gemm(p_tmp, We1, p_e1, EE, 256, 256);
    k_ln_gelu<<<EE, 256>>>(p_e1, lneg, lneb);
    gemm(p_e1, We2, Cout, EE, 64, 256);

    // Conv_agg: z = x @ Waggr ; gather-contract
    k_wagg_t<<<(64 * KD + 255) / 256, 256>>>(Wagg);
    gemm(x, p_wr, p_tmp, NN, KD, 64);   // z into g_tmp (reuse)
    k_agg<<<NN / 4, 256>>>(Cout);

    // node MLP
    gemm(p_agg, Wn1, p_n1, NN, 256, 64);
    k_ln_gelu<<<NN, 256>>>(p_n1, lnng, lnnb);
    gemm(p_n1, Wn2, xout, NN, 64, 256);
}

// round 2
// speedup vs baseline: 1.1107x; 1.1107x over previous
#include <cuda_runtime.h>
#include <cstdint>
#include <cstddef>

#define BB   128
#define NL   64
#define EE   131072
#define NN   8192
#define KD   4096

// -------------------- device scratch --------------------
__device__ float g_h5 [NN * 64];
__device__ float g_t1 [EE * 64];
__device__ float g_t2 [EE * 64];
__device__ float g_X3 [EE * 64];
__device__ float g_Y4 [EE * 64];
__device__ float g_tmp[EE * 256];      // tmp; later reused as z (NN*4096)
__device__ float g_e1 [EE * 256];      // edge hidden; later reused as CoutT (64*EE)
__device__ float g_agg[NN * 64];
__device__ float g_n1 [NN * 256];
__device__ float g_wr [64 * KD];
__device__ int   g_adj[BB * NL * NL];

// -------------------- GEMM: 128x64 tile, 8x4 microtile, 256 thr --------------------
// C[M,N] = A[M,K] @ B[K,N].  M%128==0, N%64==0, K%16==0.
__global__ void __launch_bounds__(256) k_gemm128(const float* __restrict__ A,
                                                 const float* __restrict__ B,
                                                 float* __restrict__ C,
                                                 int M, int N, int K) {
    __shared__ float As[16][136];
    __shared__ float Bs[16][64];
    const int tid = threadIdx.x;
    const int m0 = blockIdx.y * 128, n0 = blockIdx.x * 64;
    const int ty = tid >> 4, tx = tid & 15;       // microtile: rows ty*8.., cols tx*4..
    const int lm = tid >> 1, lk8 = (tid & 1) * 8; // A loader: row lm, k-offset lk8
    const int lkr = tid >> 4, lnq = tid & 15;     // B loader

    float acc[8][4] = {};

    for (int k0 = 0; k0 < K; k0 += 16) {
        const float* arow = A + (size_t)(m0 + lm) * K + k0 + lk8;
        float4 a0 = *(const float4*)(arow);
        float4 a1 = *(const float4*)(arow + 4);
        As[lk8 + 0][lm] = a0.x; As[lk8 + 1][lm] = a0.y;
        As[lk8 + 2][lm] = a0.z; As[lk8 + 3][lm] = a0.w;
        As[lk8 + 4][lm] = a1.x; As[lk8 + 5][lm] = a1.y;
        As[lk8 + 6][lm] = a1.z; As[lk8 + 7][lm] = a1.w;
        *(float4*)(&Bs[lkr][lnq * 4]) =
            *(const float4*)(B + (size_t)(k0 + lkr) * N + n0 + lnq * 4);
        __syncthreads();
#pragma unroll
        for (int k = 0; k < 16; k++) {
            float4 b  = *(const float4*)(&Bs[k][tx * 4]);
            float4 A0 = *(const float4*)(&As[k][ty * 8]);
            float4 A1 = *(const float4*)(&As[k][ty * 8 + 4]);
            float av[8] = {A0.x, A0.y, A0.z, A0.w, A1.x, A1.y, A1.z, A1.w};
#pragma unroll
            for (int r = 0; r < 8; r++) {
                acc[r][0] += av[r] * b.x;
                acc[r][1] += av[r] * b.y;
                acc[r][2] += av[r] * b.z;
                acc[r][3] += av[r] * b.w;
            }
        }
        __syncthreads();
    }
#pragma unroll
    for (int r = 0; r < 8; r++) {
        float4 o = make_float4(acc[r][0], acc[r][1], acc[r][2], acc[r][3]);
        *(float4*)(C + (size_t)(m0 + ty * 8 + r) * N + n0 + tx * 4) = o;
    }
}

// -------------------- adjacency --------------------
__global__ void k_adj_init() {
    int i = blockIdx.x * blockDim.x + threadIdx.x;
    if (i < BB * NL * NL) g_adj[i] = -1;
}
__global__ void k_adj_fill(const int* __restrict__ EI) {
    int e = blockIdx.x * blockDim.x + threadIdx.x;
    if (e >= EE) return;
    int base = EI[e];
    int li = EI[EE + e] - base;
    int lj = EI[2 * EE + e] - base;
    int b = base >> 6;
    g_adj[b * (NL * NL) + li * NL + lj] = e;
}

// -------------------- assemble tmp[:,0:192] --------------------
__global__ void k_assemble(const float* __restrict__ Cin, const int* __restrict__ EI) {
    int idx = blockIdx.x * blockDim.x + threadIdx.x;
    int e = idx >> 6, c = idx & 63;
    size_t row = (size_t)e * 256;
    g_tmp[row + c] = Cin[idx];
    g_tmp[row + 64 + c] = g_t1[idx] * g_t2[idx];
    int s = EI[EE + e], d = EI[2 * EE + e];
    g_tmp[row + 128 + c] = (s == d) ? g_h5[(size_t)s * 64 + c] : 0.0f;
}

// -------------------- tmp_mm: block per source node --------------------
// tmp[e=(li,lj), 192+c] = sum_k X3[adj(li,k),c] * Y4[adj(k,lj),c]
__global__ void __launch_bounds__(256) k_mm2() {
    __shared__ int   arow_s[64];
    __shared__ float Xs[64][65];
    const int n = blockIdx.x;          // global node = source li of graph b
    const int b = n >> 6, li = n & 63;
    const int tid = threadIdx.x;
    const int* badj = g_adj + b * (NL * NL);

    if (tid < 64) arow_s[tid] = badj[li * 64 + tid];
    __syncthreads();

    // stage X3 rows of li's out-edges
    const int c  = tid & 63;
    const int q  = tid >> 6;           // 0..3
    for (int kq = 0; kq < 16; kq++) {
        int k = kq * 4 + q;
        int e1 = arow_s[k];
        if (e1 >= 0) Xs[k][c] = g_X3[(size_t)e1 * 64 + c];
    }
    __syncthreads();

    for (int ljq = 0; ljq < 16; ljq++) {
        int lj = ljq * 4 + q;
        int eo = arow_s[lj];
        if (eo < 0) continue;
        const int* acol = badj + lj;
        float acc = 0.0f;
        for (int k = 0; k < 64; k++) {
            int e1 = arow_s[k];
            if (e1 < 0) continue;
            int e2 = acol[k * 64];
            if (e2 < 0) continue;
            acc += Xs[k][c] * g_Y4[(size_t)e2 * 64 + c];
        }
        g_tmp[(size_t)eo * 256 + 192 + c] = acc;
    }
}

// -------------------- LayerNorm(256) + exact GELU, in-place --------------------
__global__ void k_ln_gelu(float* __restrict__ data,
                          const float* __restrict__ gam,
                          const float* __restrict__ bet) {
    __shared__ float red[8];
    __shared__ float stat[2];
    size_t row = blockIdx.x;
    int t = threadIdx.x;
    float v = data[row * 256 + t];

    float s = v;
#pragma unroll
    for (int o = 16; o > 0; o >>= 1) s += __shfl_down_sync(0xffffffffu, s, o);
    if ((t & 31) == 0) red[t >> 5] = s;
    __syncthreads();
    if (t == 0) {
        float tt = 0.f;
        for (int i = 0; i < 8; i++) tt += red[i];
        stat[0] = tt * (1.0f / 256.0f);
    }
    __syncthreads();
    float mu = stat[0];
    float dv = v - mu;
    float s2 = dv * dv;
#pragma unroll
    for (int o = 16; o > 0; o >>= 1) s2 += __shfl_down_sync(0xffffffffu, s2, o);
    __syncthreads();
    if ((t & 31) == 0) red[t >> 5] = s2;
    __syncthreads();
    if (t == 0) {
        float tt = 0.f;
        for (int i = 0; i < 8; i++) tt += red[i];
        stat[1] = rsqrtf(tt * (1.0f / 256.0f) + 1e-5f);
    }
    __syncthreads();
    float y = dv * stat[1] * gam[t] + bet[t];
    float out = 0.5f * y * (1.0f + erff(y * 0.70710678118654752440f));
    data[row * 256 + t] = out;
}

// -------------------- Wagg transpose: wr[c][k*64+d] = Wagg[k][c][d] --------------------
__global__ void k_wagg_t(const float* __restrict__ W) {
    int idx = blockIdx.x * blockDim.x + threadIdx.x;
    if (idx >= 64 * KD) return;
    int k = idx >> 12, c = (idx >> 6) & 63, d = idx & 63;
    g_wr[c * KD + k * 64 + d] = W[idx];
}

// -------------------- Cout transpose: CoutT[k][e] = Cout[e][k] --------------------
__global__ void k_transpose(const float* __restrict__ Cout, float* __restrict__ CoutT) {
    __shared__ float tile[32][33];
    int e0 = blockIdx.x * 32, k0 = blockIdx.y * 32;
    int tx = threadIdx.x, ty = threadIdx.y;  // 32 x 8
#pragma unroll
    for (int j = 0; j < 4; j++)
        tile[ty + j * 8][tx] = Cout[(size_t)(e0 + ty + j * 8) * 64 + k0 + tx];
    __syncthreads();
#pragma unroll
    for (int j = 0; j < 4; j++)
        CoutT[(size_t)(k0 + ty + j * 8) * EE + e0 + tx] = tile[tx][ty + j * 8];
}

// -------------------- agg: block per graph, k-sliced z staging --------------------
// agg[(b,i),d] = sum_{s in out(i)} sum_k Cout[e_s,k] * z[(b,j_s), k*64+d]
__global__ void __launch_bounds__(512) k_agg2(const float* __restrict__ CoutT) {
    __shared__ int   s_j[64][16];
    __shared__ int   s_e[64][16];
    __shared__ int   s_deg[64];
    __shared__ float zs[64][68];
    __shared__ float cs[64][16];
    const int b = blockIdx.x;
    const int tid = threadIdx.x;
    const int i  = tid >> 3;       // 0..63
    const int dq = tid & 7;        // 8 d's per thread
    const int* badj = g_adj + b * (NL * NL);
    const float* z = g_tmp + (size_t)b * 64 * KD;

    if (tid < 64) {
        int deg = 0;
        for (int j = 0; j < 64; j++) {
            int e = badj[tid * 64 + j];
            if (e >= 0 && deg < 16) {
                s_j[tid][deg] = j;
                s_e[tid][deg] = e;
                deg++;
            }
        }
        s_deg[tid] = deg;
    }
    __syncthreads();
    const int mydeg = s_deg[i];

    float acc[8] = {};
    const int zj = tid >> 3, zc = (tid & 7) * 8;   // zs loader
    for (int k = 0; k < 64; k++) {
        // stage z slice [64 j][64 d]
        const float* zr = z + (size_t)zj * KD + k * 64 + zc;
        float4 v0 = *(const float4*)(zr);
        float4 v1 = *(const float4*)(zr + 4);
        *(float4*)(&zs[zj][zc])     = v0;
        *(float4*)(&zs[zj][zc + 4]) = v1;
        // stage Cout column k gathered by edge lists
        {
            int idx = tid;                 // 2 per thread (1024 vals)
            int ii = idx >> 4, ss = idx & 15;
            cs[ii][ss] = (ss < s_deg[ii]) ? CoutT[(size_t)k * EE + s_e[ii][ss]] : 0.0f;
            idx = tid + 512;
            ii = idx >> 4; ss = idx & 15;
            cs[ii][ss] = (ss < s_deg[ii]) ? CoutT[(size_t)k * EE + s_e[ii][ss]] : 0.0f;
        }
        __syncthreads();
#pragma unroll 4
        for (int s = 0; s < 16; s++) {
            if (s >= mydeg) break;
            int j = s_j[i][s];
            float a = cs[i][s];
            float4 z0 = *(const float4*)(&zs[j][dq * 8]);
            float4 z1 = *(const float4*)(&zs[j][dq * 8 + 4]);
            acc[0] += a * z0.x; acc[1] += a * z0.y;
            acc[2] += a * z0.z; acc[3] += a * z0.w;
            acc[4] += a * z1.x; acc[5] += a * z1.y;
            acc[6] += a * z1.z; acc[7] += a * z1.w;
        }
        __syncthreads();
    }
    float* out = g_agg + (size_t)(b * 64 + i) * 64 + dq * 8;
#pragma unroll
    for (int u = 0; u < 8; u++) out[u] = acc[u];
}

// -------------------- launch --------------------
static inline void gemm(const float* A, const float* B, float* C, int M, int N, int K) {
    dim3 g(N / 64, M / 128);
    k_gemm128<<<g, 256>>>(A, B, C, M, N, K);
}

extern "C" void kernel_launch(void* const* d_in, const int* in_sizes, int n_in,
                              void* d_out, int out_size) {
    const float* x    = (const float*)d_in[0];
    const float* Cin  = (const float*)d_in[1];
    const float* W1   = (const float*)d_in[2];
    const float* W2   = (const float*)d_in[3];
    const float* W3   = (const float*)d_in[4];
    const float* W4   = (const float*)d_in[5];
    const float* W5   = (const float*)d_in[6];
    const float* We1  = (const float*)d_in[7];
    const float* lneg = (const float*)d_in[8];
    const float* lneb = (const float*)d_in[9];
    const float* We2  = (const float*)d_in[10];
    const float* Wn1  = (const float*)d_in[11];
    const float* lnng = (const float*)d_in[12];
    const float* lnnb = (const float*)d_in[13];
    const float* Wn2  = (const float*)d_in[14];
    const float* Wagg = (const float*)d_in[15];
    const int*   EI   = (const int*)d_in[16];

    float* xout = (float*)d_out;
    float* Cout = (float*)d_out + (size_t)NN * 64;

    float *p_h5, *p_t1, *p_t2, *p_X3, *p_Y4, *p_tmp, *p_e1, *p_agg, *p_n1, *p_wr;
    cudaGetSymbolAddress((void**)&p_h5, g_h5);
    cudaGetSymbolAddress((void**)&p_t1, g_t1);
    cudaGetSymbolAddress((void**)&p_t2, g_t2);
    cudaGetSymbolAddress((void**)&p_X3, g_X3);
    cudaGetSymbolAddress((void**)&p_Y4, g_Y4);
    cudaGetSymbolAddress((void**)&p_tmp, g_tmp);
    cudaGetSymbolAddress((void**)&p_e1, g_e1);
    cudaGetSymbolAddress((void**)&p_agg, g_agg);
    cudaGetSymbolAddress((void**)&p_n1, g_n1);
    cudaGetSymbolAddress((void**)&p_wr, g_wr);

    // adjacency
    k_adj_init<<<(BB * NL * NL + 255) / 256, 256>>>();
    k_adj_fill<<<(EE + 255) / 256, 256>>>(EI);

    // pre-GEMMs
    gemm(x,   W5, p_h5, NN, 64, 64);
    gemm(Cin, W1, p_t1, EE, 64, 64);
    gemm(Cin, W2, p_t2, EE, 64, 64);
    gemm(Cin, W3, p_X3, EE, 64, 64);
    gemm(Cin, W4, p_Y4, EE, 64, 64);

    // assemble tmp
    k_assemble<<<(EE * 64) / 256, 256>>>(Cin, EI);
    k_mm2<<<NN, 256>>>();

    // edge MLP
    gemm(p_tmp, We1, p_e1, EE, 256, 256);
    k_ln_gelu<<<EE, 256>>>(p_e1, lneg, lneb);
    gemm(p_e1, We2, Cout, EE, 64, 256);

    // Conv_agg
    float* p_ct = p_e1;   // reuse e1 buffer for CoutT [64][EE]
    k_transpose<<<dim3(EE / 32, 2), dim3(32, 8)>>>(Cout, p_ct);
    k_wagg_t<<<(64 * KD + 255) / 256, 256>>>(Wagg);
    gemm(x, p_wr, p_tmp, NN, KD, 64);   // z into g_tmp
    k_agg2<<<BB, 512>>>(p_ct);

    // node MLP
    gemm(p_agg, Wn1, p_n1, NN, 256, 64);
    k_ln_gelu<<<NN, 256>>>(p_n1, lnng, lnnb);
    gemm(p_n1, Wn2, xout, NN, 64, 256);
}

// round 4
// speedup vs baseline: 1.1884x; 1.0699x over previous
#include <cuda_runtime.h>
#include <cstdint>
#include <cstddef>

#define BB 128
#define NL 64
#define EE 131072
#define NN 8192
#define KD 4096

// -------------------- device scratch --------------------
__device__ float g_h5 [NN * 64];
__device__ float g_t1 [EE * 64];
__device__ float g_t2 [EE * 64];
__device__ float g_X3 [EE * 64];
__device__ float g_Y4 [EE * 64];
__device__ float g_tmp[EE * 256];      // tmp; later reused as z (NN*4096)
__device__ float g_e1 [EE * 256];      // edge hidden; later reused as CoutT (64*EE)
__device__ float g_agg[NN * 64];
__device__ float g_n1 [NN * 256];
__device__ float g_wr [64 * KD];       // wr[c][k*64+d] = Wagg[k][c][d]
__device__ int   g_adj[BB * NL * NL];

// -------------------- helpers --------------------
__device__ __forceinline__ uint32_t tf32r(float f) {
    uint32_t r;
    asm("cvt.rna.tf32.f32 %0, %1;" : "=r"(r) : "f"(f));
    return r;
}
__device__ __forceinline__ void split32(float v, uint32_t& h, uint32_t& l) {
    h = tf32r(v);
    l = tf32r(v - __uint_as_float(h));
}
__device__ __forceinline__ void mma8(float* c, const uint32_t* a, const uint32_t* b) {
    asm volatile(
        "mma.sync.aligned.m16n8k8.row.col.f32.tf32.tf32.f32 "
        "{%0,%1,%2,%3}, {%4,%5,%6,%7}, {%8,%9}, {%0,%1,%2,%3};"
        : "+f"(c[0]), "+f"(c[1]), "+f"(c[2]), "+f"(c[3])
        : "r"(a[0]), "r"(a[1]), "r"(a[2]), "r"(a[3]), "r"(b[0]), "r"(b[1]));
}

// ==================== 3xTF32 mma.sync GEMM ====================
// C[M,N] = A[M,K] @ B[K,N]  (both row-major). M%128==0, N%64==0, K%32==0.
// CTA 128x64 tile, 256 thr, 8 warps (4m x 2n), warp tile 32x32.
__global__ void __launch_bounds__(256) k_gemm_mma(const float* __restrict__ A,
                                                  const float* __restrict__ B,
                                                  float* __restrict__ C,
                                                  int M, int N, int K) {
    __shared__ float As[128][36];
    __shared__ float Bs[32][72];
    const int tid = threadIdx.x;
    const int lane = tid & 31, wid = tid >> 5;
    const int wm = wid & 3, wn = wid >> 2;      // warp grid 4x2
    const int g = lane >> 2, q = lane & 3;
    const int m0 = blockIdx.x * 128, n0 = blockIdx.y * 64;

    // loaders
    const int ar = tid >> 3, ac = (tid & 7) * 4;
    const int bk = tid >> 4, bn = (tid & 15) * 4;

    float acc[2][4][4] = {};

    for (int k0 = 0; k0 < K; k0 += 32) {
#pragma unroll
        for (int i = 0; i < 4; i++)
            *(float4*)(&As[ar + i * 32][ac]) =
                *(const float4*)(A + (size_t)(m0 + ar + i * 32) * K + k0 + ac);
#pragma unroll
        for (int i = 0; i < 2; i++)
            *(float4*)(&Bs[bk + i * 16][bn]) =
                *(const float4*)(B + (size_t)(k0 + bk + i * 16) * N + n0 + bn);
        __syncthreads();

#pragma unroll
        for (int kk = 0; kk < 32; kk += 8) {
            uint32_t ah[2][4], al[2][4], bh[4][2], bl[4][2];
#pragma unroll
            for (int mt = 0; mt < 2; mt++) {
                const int row = wm * 32 + mt * 16 + g;
                split32(As[row][kk + q],          ah[mt][0], al[mt][0]);
                split32(As[row + 8][kk + q],      ah[mt][1], al[mt][1]);
                split32(As[row][kk + q + 4],      ah[mt][2], al[mt][2]);
                split32(As[row + 8][kk + q + 4],  ah[mt][3], al[mt][3]);
            }
#pragma unroll
            for (int nt = 0; nt < 4; nt++) {
                const int col = wn * 32 + nt * 8 + g;
                split32(Bs[kk + q][col],     bh[nt][0], bl[nt][0]);
                split32(Bs[kk + q + 4][col], bh[nt][1], bl[nt][1]);
            }
#pragma unroll
            for (int mt = 0; mt < 2; mt++)
#pragma unroll
                for (int nt = 0; nt < 4; nt++) {
                    mma8(acc[mt][nt], ah[mt], bh[nt]);
                    mma8(acc[mt][nt], ah[mt], bl[nt]);
                    mma8(acc[mt][nt], al[mt], bh[nt]);
                }
        }
        __syncthreads();
    }

#pragma unroll
    for (int mt = 0; mt < 2; mt++) {
        const int row = m0 + wm * 32 + mt * 16 + g;
#pragma unroll
        for (int nt = 0; nt < 4; nt++) {
            const int col = n0 + wn * 32 + nt * 8 + q * 2;
            *(float2*)(C + (size_t)row * N + col) =
                make_float2(acc[mt][nt][0], acc[mt][nt][1]);
            *(float2*)(C + (size_t)(row + 8) * N + col) =
                make_float2(acc[mt][nt][2], acc[mt][nt][3]);
        }
    }
}

// -------------------- adjacency --------------------
__global__ void k_adj_init() {
    int i = blockIdx.x * blockDim.x + threadIdx.x;
    if (i < BB * NL * NL) g_adj[i] = -1;
}
__global__ void k_adj_fill(const int* __restrict__ EI) {
    int e = blockIdx.x * blockDim.x + threadIdx.x;
    if (e >= EE) return;
    int base = EI[e];
    int li = EI[EE + e] - base;
    int lj = EI[2 * EE + e] - base;
    int b = base >> 6;
    g_adj[b * (NL * NL) + li * NL + lj] = e;
}

// -------------------- assemble tmp[:,0:192] --------------------
__global__ void k_assemble(const float* __restrict__ Cin, const int* __restrict__ EI) {
    int idx = blockIdx.x * blockDim.x + threadIdx.x;
    int e = idx >> 6, c = idx & 63;
    size_t row = (size_t)e * 256;
    g_tmp[row + c] = Cin[idx];
    g_tmp[row + 64 + c] = g_t1[idx] * g_t2[idx];
    int s = EI[EE + e], d = EI[2 * EE + e];
    g_tmp[row + 128 + c] = (s == d) ? g_h5[(size_t)s * 64 + c] : 0.0f;
}

// -------------------- tmp_mm --------------------
__global__ void __launch_bounds__(256) k_mm2() {
    __shared__ int   arow_s[64];
    __shared__ float Xs[64][65];
    const int n = blockIdx.x;
    const int b = n >> 6, li = n & 63;
    const int tid = threadIdx.x;
    const int* badj = g_adj + b * (NL * NL);

    if (tid < 64) arow_s[tid] = badj[li * 64 + tid];
    __syncthreads();
    const int c = tid & 63;
    const int q = tid >> 6;
    for (int kq = 0; kq < 16; kq++) {
        int k = kq * 4 + q;
        int e1 = arow_s[k];
        if (e1 >= 0) Xs[k][c] = g_X3[(size_t)e1 * 64 + c];
    }
    __syncthreads();
    for (int ljq = 0; ljq < 16; ljq++) {
        int lj = ljq * 4 + q;
        int eo = arow_s[lj];
        if (eo < 0) continue;
        const int* acol = badj + lj;
        float acc = 0.0f;
        for (int k = 0; k < 64; k++) {
            int e1 = arow_s[k];
            if (e1 < 0) continue;
            int e2 = acol[k * 64];
            if (e2 < 0) continue;
            acc += Xs[k][c] * g_Y4[(size_t)e2 * 64 + c];
        }
        g_tmp[(size_t)eo * 256 + 192 + c] = acc;
    }
}

// -------------------- LayerNorm(256) + exact GELU, in-place --------------------
__global__ void k_ln_gelu(float* __restrict__ data,
                          const float* __restrict__ gam,
                          const float* __restrict__ bet) {
    __shared__ float red[8];
    __shared__ float stat[2];
    size_t row = blockIdx.x;
    int t = threadIdx.x;
    float v = data[row * 256 + t];

    float s = v;
#pragma unroll
    for (int o = 16; o > 0; o >>= 1) s += __shfl_down_sync(0xffffffffu, s, o);
    if ((t & 31) == 0) red[t >> 5] = s;
    __syncthreads();
    if (t == 0) {
        float tt = 0.f;
        for (int i = 0; i < 8; i++) tt += red[i];
        stat[0] = tt * (1.0f / 256.0f);
    }
    __syncthreads();
    float mu = stat[0];
    float dv = v - mu;
    float s2 = dv * dv;
#pragma unroll
    for (int o = 16; o > 0; o >>= 1) s2 += __shfl_down_sync(0xffffffffu, s2, o);
    __syncthreads();
    if ((t & 31) == 0) red[t >> 5] = s2;
    __syncthreads();
    if (t == 0) {
        float tt = 0.f;
        for (int i = 0; i < 8; i++) tt += red[i];
        stat[1] = rsqrtf(tt * (1.0f / 256.0f) + 1e-5f);
    }
    __syncthreads();
    float y = dv * stat[1] * gam[t] + bet[t];
    float out = 0.5f * y * (1.0f + erff(y * 0.70710678118654752440f));
    data[row * 256 + t] = out;
}

// -------------------- Wagg reshape: wr[c][k*64+d] = Wagg[k][c][d] --------------------
__global__ void k_wagg_t(const float* __restrict__ W) {
    int idx = blockIdx.x * blockDim.x + threadIdx.x;
    if (idx >= 64 * KD) return;
    int k = idx >> 12, c = (idx >> 6) & 63, d = idx & 63;
    g_wr[c * KD + k * 64 + d] = W[idx];
}

// -------------------- Cout transpose --------------------
__global__ void k_transpose(const float* __restrict__ Cout, float* __restrict__ CoutT) {
    __shared__ float tile[32][33];
    int e0 = blockIdx.x * 32, k0 = blockIdx.y * 32;
    int tx = threadIdx.x, ty = threadIdx.y;
#pragma unroll
    for (int j = 0; j < 4; j++)
        tile[ty + j * 8][tx] = Cout[(size_t)(e0 + ty + j * 8) * 64 + k0 + tx];
    __syncthreads();
#pragma unroll
    for (int j = 0; j < 4; j++)
        CoutT[(size_t)(k0 + ty + j * 8) * EE + e0 + tx] = tile[tx][ty + j * 8];
}

// -------------------- agg --------------------
__global__ void __launch_bounds__(512) k_agg2(const float* __restrict__ CoutT) {
    __shared__ int   s_j[64][16];
    __shared__ int   s_e[64][16];
    __shared__ int   s_deg[64];
    __shared__ float zs[64][68];
    __shared__ float cs[64][16];
    const int b = blockIdx.x;
    const int tid = threadIdx.x;
    const int i = tid >> 3;
    const int dq = tid & 7;
    const int* badj = g_adj + b * (NL * NL);
    const float* z = g_tmp + (size_t)b * 64 * KD;

    if (tid < 64) {
        int deg = 0;
        for (int j = 0; j < 64; j++) {
            int e = badj[tid * 64 + j];
            if (e >= 0 && deg < 16) {
                s_j[tid][deg] = j;
                s_e[tid][deg] = e;
                deg++;
            }
        }
        s_deg[tid] = deg;
    }
    __syncthreads();
    const int mydeg = s_deg[i];

    float acc[8] = {};
    const int zj = tid >> 3, zc = (tid & 7) * 8;
    for (int k = 0; k < 64; k++) {
        const float* zr = z + (size_t)zj * KD + k * 64 + zc;
        float4 v0 = *(const float4*)(zr);
        float4 v1 = *(const float4*)(zr + 4);
        *(float4*)(&zs[zj][zc])     = v0;
        *(float4*)(&zs[zj][zc + 4]) = v1;
        {
            int idx = tid;
            int ii = idx >> 4, ss = idx & 15;
            cs[ii][ss] = (ss < s_deg[ii]) ? CoutT[(size_t)k * EE + s_e[ii][ss]] : 0.0f;
            idx = tid + 512;
            ii = idx >> 4; ss = idx & 15;
            cs[ii][ss] = (ss < s_deg[ii]) ? CoutT[(size_t)k * EE + s_e[ii][ss]] : 0.0f;
        }
        __syncthreads();
#pragma unroll 4
        for (int s = 0; s < 16; s++) {
            if (s >= mydeg) break;
            int j = s_j[i][s];
            float a = cs[i][s];
            float4 z0 = *(const float4*)(&zs[j][dq * 8]);
            float4 z1 = *(const float4*)(&zs[j][dq * 8 + 4]);
            acc[0] += a * z0.x; acc[1] += a * z0.y;
            acc[2] += a * z0.z; acc[3] += a * z0.w;
            acc[4] += a * z1.x; acc[5] += a * z1.y;
            acc[6] += a * z1.z; acc[7] += a * z1.w;
        }
        __syncthreads();
    }
    float* out = g_agg + (size_t)(b * 64 + i) * 64 + dq * 8;
#pragma unroll
    for (int u = 0; u < 8; u++) out[u] = acc[u];
}

// -------------------- launch --------------------
static inline void gemm(const float* A, const float* B, float* C, int M, int N, int K) {
    dim3 grd(M / 128, N / 64);
    k_gemm_mma<<<grd, 256>>>(A, B, C, M, N, K);
}

extern "C" void kernel_launch(void* const* d_in, const int* in_sizes, int n_in,
                              void* d_out, int out_size) {
    const float* x    = (const float*)d_in[0];
    const float* Cin  = (const float*)d_in[1];
    const float* W1   = (const float*)d_in[2];
    const float* W2   = (const float*)d_in[3];
    const float* W3   = (const float*)d_in[4];
    const float* W4   = (const float*)d_in[5];
    const float* W5   = (const float*)d_in[6];
    const float* We1  = (const float*)d_in[7];
    const float* lneg = (const float*)d_in[8];
    const float* lneb = (const float*)d_in[9];
    const float* We2  = (const float*)d_in[10];
    const float* Wn1  = (const float*)d_in[11];
    const float* lnng = (const float*)d_in[12];
    const float* lnnb = (const float*)d_in[13];
    const float* Wn2  = (const float*)d_in[14];
    const float* Wagg = (const float*)d_in[15];
    const int*   EI   = (const int*)d_in[16];

    float* xout = (float*)d_out;
    float* Cout = (float*)d_out + (size_t)NN * 64;

    float *p_h5, *p_t1, *p_t2, *p_X3, *p_Y4, *p_tmp, *p_e1, *p_agg, *p_n1, *p_wr;
    cudaGetSymbolAddress((void**)&p_h5, g_h5);
    cudaGetSymbolAddress((void**)&p_t1, g_t1);
    cudaGetSymbolAddress((void**)&p_t2, g_t2);
    cudaGetSymbolAddress((void**)&p_X3, g_X3);
    cudaGetSymbolAddress((void**)&p_Y4, g_Y4);
    cudaGetSymbolAddress((void**)&p_tmp, g_tmp);
    cudaGetSymbolAddress((void**)&p_e1, g_e1);
    cudaGetSymbolAddress((void**)&p_agg, g_agg);
    cudaGetSymbolAddress((void**)&p_n1, g_n1);
    cudaGetSymbolAddress((void**)&p_wr, g_wr);

    // adjacency
    k_adj_init<<<(BB * NL * NL + 255) / 256, 256>>>();
    k_adj_fill<<<(EE + 255) / 256, 256>>>(EI);

    // pre-GEMMs (tensor via mma.sync tf32 3x)
    gemm(x,   W5, p_h5, NN, 64, 64);
    gemm(Cin, W1, p_t1, EE, 64, 64);
    gemm(Cin, W2, p_t2, EE, 64, 64);
    gemm(Cin, W3, p_X3, EE, 64, 64);
    gemm(Cin, W4, p_Y4, EE, 64, 64);

    // assemble tmp
    k_assemble<<<(EE * 64) / 256, 256>>>(Cin, EI);
    k_mm2<<<NN, 256>>>();

    // edge MLP
    gemm(p_tmp, We1, p_e1, EE, 256, 256);
    k_ln_gelu<<<EE, 256>>>(p_e1, lneg, lneb);
    gemm(p_e1, We2, Cout, EE, 64, 256);

    // Conv_agg
    float* p_ct = p_e1;   // reuse e1 buffer for CoutT [64][EE]
    k_transpose<<<dim3(EE / 32, 2), dim3(32, 8)>>>(Cout, p_ct);
    k_wagg_t<<<(64 * KD + 255) / 256, 256>>>(Wagg);
    gemm(x, p_wr, p_tmp, NN, KD, 64);   // z into g_tmp
    k_agg2<<<BB, 512>>>(p_ct);

    // node MLP
    gemm(p_agg, Wn1, p_n1, NN, 256, 64);
    k_ln_gelu<<<NN, 256>>>(p_n1, lnng, lnnb);
    gemm(p_n1, Wn2, xout, NN, 64, 256);
}